// round 13
// baseline (speedup 1.0000x reference)
#include <cuda_runtime.h>
#include <cuda_fp16.h>
#include <cstdint>

#define N_NODES 100000
#define N_EDGES 1600000
#define EMB 128
#define HID 128
#define REPR 64
#define CAT 384

#define SCAN_B 256
#define SCAN_NBLK ((N_NODES + SCAN_B - 1) / SCAN_B)   // 391

#define NCHUNK 4
#define CHUNK 25088   // multiple of 128; 4*25088 >= N_NODES

// Scratch (device globals; no allocation APIs allowed)
__device__ int    g_is64;
__device__ int    g_cnt   [N_NODES];
__device__ int    g_cursor[N_NODES];
__device__ int    g_ro    [N_NODES];
__device__ int    g_adj   [N_EDGES];
__device__ int    g_bsum  [SCAN_NBLK];
__device__ int    g_boff  [SCAN_NBLK];
__device__ float  g_dinv  [N_NODES];
__device__ __half g_h1a   [(size_t)N_NODES * HID];  // h1 ping buffer (layers 0,2)
__device__ __half g_h1b   [(size_t)N_NODES * HID];  // h1 pong buffer (layer 1)
__device__ __half g_xsh   [(size_t)N_NODES * CAT];  // fp16 JumpingKnowledge concat

// ---------------------------------------------------------------------------
// Helpers
// ---------------------------------------------------------------------------
__device__ __forceinline__ uint32_t tf32r(float f) {
    uint32_t u;
    asm("cvt.rna.tf32.f32 %0, %1;" : "=r"(u) : "f"(f));
    return u;
}

__device__ __forceinline__ void mma_tf32(float c[4], const uint32_t a[4],
                                         uint32_t b0, uint32_t b1) {
    asm volatile(
        "mma.sync.aligned.m16n8k8.row.col.f32.tf32.tf32.f32 "
        "{%0,%1,%2,%3}, {%4,%5,%6,%7}, {%8,%9}, {%0,%1,%2,%3};"
        : "+f"(c[0]), "+f"(c[1]), "+f"(c[2]), "+f"(c[3])
        : "r"(a[0]), "r"(a[1]), "r"(a[2]), "r"(a[3]), "r"(b0), "r"(b1));
}

__device__ __forceinline__ int edge_at(const void* ei, int idx) {
    if (g_is64) return (int)((const long long*)ei)[idx];
    return ((const int*)ei)[idx];
}

__device__ __forceinline__ __half* h1buf(int l) {
    return (l & 1) ? g_h1b : g_h1a;
}

// ---------------------------------------------------------------------------
// Prep: zero counters; probe edge-index dtype (int64 nonneg < 2^32 has zero
// high words).
// ---------------------------------------------------------------------------
__global__ void k_prep(const int* __restrict__ ei32) {
    int i = blockIdx.x * blockDim.x + threadIdx.x;
    if (i < N_NODES) { g_cnt[i] = 0; g_cursor[i] = 0; }
    if (blockIdx.x == 0 && threadIdx.x == 0) {
        int is64 = 1;
        for (int k = 0; k < 256; k++) {
            if (ei32[2 * k + 1] != 0) { is64 = 0; break; }
        }
        g_is64 = is64;
    }
}

__global__ void k_count(const void* __restrict__ ei) {
    int e = blockIdx.x * blockDim.x + threadIdx.x;
    if (e < N_EDGES) {
        int c = edge_at(ei, N_EDGES + e);
        atomicAdd(&g_cnt[c], 1);
    }
}

__global__ void __launch_bounds__(SCAN_B) k_block_sums() {
    __shared__ int sdata[SCAN_B];
    int i = blockIdx.x * SCAN_B + threadIdx.x;
    int v = (i < N_NODES) ? g_cnt[i] : 0;
    sdata[threadIdx.x] = v;
    __syncthreads();
#pragma unroll
    for (int off = SCAN_B / 2; off > 0; off >>= 1) {
        if (threadIdx.x < off) sdata[threadIdx.x] += sdata[threadIdx.x + off];
        __syncthreads();
    }
    if (threadIdx.x == 0) g_bsum[blockIdx.x] = sdata[0];
}

__global__ void __launch_bounds__(512) k_scan_bsums() {
    __shared__ int s[512];
    int t = threadIdx.x;
    int v = (t < SCAN_NBLK) ? g_bsum[t] : 0;
    s[t] = v;
    __syncthreads();
    for (int off = 1; off < 512; off <<= 1) {
        int u = (t >= off) ? s[t - off] : 0;
        __syncthreads();
        s[t] += u;
        __syncthreads();
    }
    if (t < SCAN_NBLK) g_boff[t] = s[t] - v;   // exclusive
}

__global__ void __launch_bounds__(SCAN_B) k_scan_final() {
    __shared__ int s[SCAN_B];
    int t = threadIdx.x;
    int i = blockIdx.x * SCAN_B + t;
    int v = (i < N_NODES) ? g_cnt[i] : 0;
    s[t] = v;
    __syncthreads();
    for (int off = 1; off < SCAN_B; off <<= 1) {
        int u = (t >= off) ? s[t - off] : 0;
        __syncthreads();
        s[t] += u;
        __syncthreads();
    }
    if (i < N_NODES) {
        g_ro[i]   = g_boff[blockIdx.x] + s[t] - v;   // exclusive
        g_dinv[i] = rsqrtf(1.0f + (float)v);
    }
}

__global__ void k_csr_fill(const void* __restrict__ ei) {
    int e = blockIdx.x * blockDim.x + threadIdx.x;
    if (e < N_EDGES) {
        int r = edge_at(ei, e);
        int c = edge_at(ei, N_EDGES + e);
        int pos = atomicAdd(&g_cursor[c], 1);
        g_adj[g_ro[c] + pos] = r;
    }
}

// ---------------------------------------------------------------------------
// Layer GEMM (tf32): h1buf(layer) = fp16( (A @ W) * dinv[row] ),
// rows [node_off, node_lim)
// layer 0: A = x (fp32); layer > 0: A = g_xsh slice (fp16, exact in tf32)
// ---------------------------------------------------------------------------
__global__ void __launch_bounds__(256) k_gemm_layer(
    const float* __restrict__ x, int layer,
    const float* __restrict__ W,
    int node_off, int node_lim)
{
    __shared__ float As[128][36];
    __shared__ float Ws[32][132];

    const int row0   = node_off + blockIdx.x * 128;
    const int tid    = threadIdx.x;
    const int wid    = tid >> 5;
    const int lane   = tid & 31;
    const int g      = lane >> 2;
    const int t      = lane & 3;
    const int warp_m = wid >> 1;
    const int warp_n = wid & 1;

    const __half* Ah = (layer > 0) ? (g_xsh + (layer - 1) * HID) : nullptr;
    __half* H = h1buf(layer);

    float acc[2][8][4];
#pragma unroll
    for (int mt = 0; mt < 2; mt++)
#pragma unroll
        for (int nt = 0; nt < 8; nt++)
#pragma unroll
            for (int q = 0; q < 4; q++) acc[mt][nt][q] = 0.0f;

    for (int k0 = 0; k0 < 128; k0 += 32) {
#pragma unroll
        for (int p = 0; p < 4; p++) {
            int idx = tid + p * 256;
            int r   = idx >> 3;
            int c4  = (idx & 7) << 2;
            int gr  = row0 + r;
            float4 v = make_float4(0.f, 0.f, 0.f, 0.f);
            if (gr < node_lim) {
                if (layer == 0) {
                    v = *(const float4*)(x + (size_t)gr * EMB + k0 + c4);
                    v.x = __uint_as_float(tf32r(v.x));
                    v.y = __uint_as_float(tf32r(v.y));
                    v.z = __uint_as_float(tf32r(v.z));
                    v.w = __uint_as_float(tf32r(v.w));
                } else {
                    uint2 u = *(const uint2*)(Ah + (size_t)gr * CAT + k0 + c4);
                    float2 f0 = __half22float2(*(__half2*)&u.x);
                    float2 f1 = __half22float2(*(__half2*)&u.y);
                    v = make_float4(f0.x, f0.y, f1.x, f1.y);
                }
            }
            *(float4*)&As[r][c4] = v;
        }
#pragma unroll
        for (int p = 0; p < 4; p++) {
            int idx = tid + p * 256;
            int r   = idx >> 5;
            int c4  = (idx & 31) << 2;
            float4 v = *(const float4*)(W + (size_t)(k0 + r) * 128 + c4);
            v.x = __uint_as_float(tf32r(v.x));
            v.y = __uint_as_float(tf32r(v.y));
            v.z = __uint_as_float(tf32r(v.z));
            v.w = __uint_as_float(tf32r(v.w));
            *(float4*)&Ws[r][c4] = v;
        }
        __syncthreads();

#pragma unroll
        for (int kc = 0; kc < 4; kc++) {
            int kb = kc * 8;
            uint32_t afr[2][4];
#pragma unroll
            for (int mt = 0; mt < 2; mt++) {
                int mrow = warp_m * 32 + mt * 16;
                afr[mt][0] = __float_as_uint(As[mrow + g    ][kb + t    ]);
                afr[mt][1] = __float_as_uint(As[mrow + g + 8][kb + t    ]);
                afr[mt][2] = __float_as_uint(As[mrow + g    ][kb + t + 4]);
                afr[mt][3] = __float_as_uint(As[mrow + g + 8][kb + t + 4]);
            }
#pragma unroll
            for (int nt = 0; nt < 8; nt++) {
                int nc = warp_n * 64 + nt * 8;
                uint32_t b0 = __float_as_uint(Ws[kb + t    ][nc + g]);
                uint32_t b1 = __float_as_uint(Ws[kb + t + 4][nc + g]);
                mma_tf32(acc[0][nt], afr[0], b0, b1);
                mma_tf32(acc[1][nt], afr[1], b0, b1);
            }
        }
        __syncthreads();
    }

#pragma unroll
    for (int mt = 0; mt < 2; mt++) {
        int r0 = row0 + warp_m * 32 + mt * 16 + g;
        int r1 = r0 + 8;
        bool ok0 = (r0 < node_lim), ok1 = (r1 < node_lim);
        float d0 = ok0 ? g_dinv[r0] : 0.f;
        float d1 = ok1 ? g_dinv[r1] : 0.f;
#pragma unroll
        for (int nt = 0; nt < 8; nt++) {
            int col = warp_n * 64 + nt * 8 + 2 * t;
            if (ok0) {
                __half2 h = __floats2half2_rn(acc[mt][nt][0] * d0, acc[mt][nt][1] * d0);
                *(__half2*)(H + (size_t)r0 * 128 + col) = h;
            }
            if (ok1) {
                __half2 h = __floats2half2_rn(acc[mt][nt][2] * d1, acc[mt][nt][3] * d1);
                *(__half2*)(H + (size_t)r1 * 128 + col) = h;
            }
        }
    }
}

// ---------------------------------------------------------------------------
// Gather aggregation for nodes [node_off, node_lim): warp per node, unroll 8.
// Reads h1buf(layer) (all rows), writes xs rows of this chunk.
// ---------------------------------------------------------------------------
__global__ void __launch_bounds__(256) k_gather(
    const float* __restrict__ b, int layer, int node_off, int node_lim)
{
    int w    = node_off + ((blockIdx.x * 256 + threadIdx.x) >> 5);
    int lane = threadIdx.x & 31;
    if (w >= node_lim) return;

    const __half* H = h1buf(layer);

    float4 acc;
    {
        uint2 u = ((const uint2*)(H + (size_t)w * 128))[lane];
        float2 f0 = __half22float2(*(__half2*)&u.x);
        float2 f1 = __half22float2(*(__half2*)&u.y);
        acc = make_float4(f0.x, f0.y, f1.x, f1.y);
    }

    int start = g_ro[w];
    int deg   = g_cnt[w];

    int k = 0;
    for (; k + 7 < deg; k += 8) {
        int n[8];
#pragma unroll
        for (int j = 0; j < 8; j++) n[j] = g_adj[start + k + j];
        uint2 u[8];
#pragma unroll
        for (int j = 0; j < 8; j++)
            u[j] = ((const uint2*)(H + (size_t)n[j] * 128))[lane];
#pragma unroll
        for (int j = 0; j < 8; j++) {
            float2 f0 = __half22float2(*(__half2*)&u[j].x);
            float2 f1 = __half22float2(*(__half2*)&u[j].y);
            acc.x += f0.x; acc.y += f0.y; acc.z += f1.x; acc.w += f1.y;
        }
    }
    for (; k + 3 < deg; k += 4) {
        int n[4];
#pragma unroll
        for (int j = 0; j < 4; j++) n[j] = g_adj[start + k + j];
        uint2 u[4];
#pragma unroll
        for (int j = 0; j < 4; j++)
            u[j] = ((const uint2*)(H + (size_t)n[j] * 128))[lane];
#pragma unroll
        for (int j = 0; j < 4; j++) {
            float2 f0 = __half22float2(*(__half2*)&u[j].x);
            float2 f1 = __half22float2(*(__half2*)&u[j].y);
            acc.x += f0.x; acc.y += f0.y; acc.z += f1.x; acc.w += f1.y;
        }
    }
    for (; k < deg; k++) {
        int n0 = g_adj[start + k];
        uint2 u0 = ((const uint2*)(H + (size_t)n0 * 128))[lane];
        float2 f0 = __half22float2(*(__half2*)&u0.x);
        float2 f1 = __half22float2(*(__half2*)&u0.y);
        acc.x += f0.x; acc.y += f0.y; acc.z += f1.x; acc.w += f1.y;
    }

    float d = g_dinv[w];
    float4 bv = ((const float4*)b)[lane];
    float4 r;
    r.x = fmaxf(fmaf(acc.x, d, bv.x), 0.f);
    r.y = fmaxf(fmaf(acc.y, d, bv.y), 0.f);
    r.z = fmaxf(fmaf(acc.z, d, bv.z), 0.f);
    r.w = fmaxf(fmaf(acc.w, d, bv.w), 0.f);

    uint2 o;
    __half2 h0 = __floats2half2_rn(r.x, r.y);
    __half2 h1 = __floats2half2_rn(r.z, r.w);
    o.x = *(uint32_t*)&h0;
    o.y = *(uint32_t*)&h1;
    *((uint2*)(g_xsh + (size_t)w * CAT + layer * HID) + lane) = o;
}

// ---------------------------------------------------------------------------
// Final GEMM (tf32): out = xsh @ Wlin + blin, rows [node_off, node_lim)
// ---------------------------------------------------------------------------
__global__ void __launch_bounds__(256) k_gemm_final(
    const float* __restrict__ W,
    const float* __restrict__ b,
    float* __restrict__ out,
    int node_off, int node_lim)
{
    __shared__ float As[128][36];
    __shared__ float Ws[32][68];

    const int row0 = node_off + blockIdx.x * 128;
    const int tid  = threadIdx.x;
    const int wid  = tid >> 5;
    const int lane = tid & 31;
    const int g    = lane >> 2;
    const int t    = lane & 3;

    float acc[8][4];
#pragma unroll
    for (int nt = 0; nt < 8; nt++)
#pragma unroll
        for (int q = 0; q < 4; q++) acc[nt][q] = 0.0f;

    for (int k0 = 0; k0 < CAT; k0 += 32) {
#pragma unroll
        for (int p = 0; p < 4; p++) {
            int idx = tid + p * 256;
            int r   = idx >> 3;
            int c4  = (idx & 7) << 2;
            int gr  = row0 + r;
            float4 v = make_float4(0.f, 0.f, 0.f, 0.f);
            if (gr < node_lim) {
                uint2 u = *(const uint2*)(g_xsh + (size_t)gr * CAT + k0 + c4);
                float2 f0 = __half22float2(*(__half2*)&u.x);
                float2 f1 = __half22float2(*(__half2*)&u.y);
                v = make_float4(f0.x, f0.y, f1.x, f1.y);
            }
            *(float4*)&As[r][c4] = v;
        }
#pragma unroll
        for (int p = 0; p < 2; p++) {
            int idx = tid + p * 256;
            int r   = idx >> 4;
            int c4  = (idx & 15) << 2;
            float4 v = *(const float4*)(W + (size_t)(k0 + r) * REPR + c4);
            v.x = __uint_as_float(tf32r(v.x));
            v.y = __uint_as_float(tf32r(v.y));
            v.z = __uint_as_float(tf32r(v.z));
            v.w = __uint_as_float(tf32r(v.w));
            *(float4*)&Ws[r][c4] = v;
        }
        __syncthreads();

#pragma unroll
        for (int kc = 0; kc < 4; kc++) {
            int kb = kc * 8;
            uint32_t afr[4];
            int mrow = wid * 16;
            afr[0] = __float_as_uint(As[mrow + g    ][kb + t    ]);
            afr[1] = __float_as_uint(As[mrow + g + 8][kb + t    ]);
            afr[2] = __float_as_uint(As[mrow + g    ][kb + t + 4]);
            afr[3] = __float_as_uint(As[mrow + g + 8][kb + t + 4]);
#pragma unroll
            for (int nt = 0; nt < 8; nt++) {
                int nc = nt * 8;
                uint32_t b0 = __float_as_uint(Ws[kb + t    ][nc + g]);
                uint32_t b1 = __float_as_uint(Ws[kb + t + 4][nc + g]);
                mma_tf32(acc[nt], afr, b0, b1);
            }
        }
        __syncthreads();
    }

    int r0 = row0 + wid * 16 + g;
    int r1 = r0 + 8;
    bool ok0 = (r0 < node_lim), ok1 = (r1 < node_lim);
#pragma unroll
    for (int nt = 0; nt < 8; nt++) {
        int col = nt * 8 + 2 * t;
        float2 bv = *(const float2*)(b + col);
        if (ok0) {
            float2 v = make_float2(acc[nt][0] + bv.x, acc[nt][1] + bv.y);
            *(float2*)(out + (size_t)r0 * REPR + col) = v;
        }
        if (ok1) {
            float2 v = make_float2(acc[nt][2] + bv.x, acc[nt][3] + bv.y);
            *(float2*)(out + (size_t)r1 * REPR + col) = v;
        }
    }
}

// ---------------------------------------------------------------------------
// Launch. Chunked software pipeline across two streams with DOUBLE-BUFFERED
// h1: gemm(l+1) writes h1[(l+1)&1] while gather(l) still reads h1[l&1], so
// the per-chunk overlap is race-free:
//   gather(l, c) reads h1[l&1] (all rows) -> writes xs rows c   [stream A]
//   gemm(l+1, c) reads xs rows c -> writes h1[(l+1)&1] rows c   [stream B]
// gather(l+1) waits for all gemm(l+1) chunks (evB join).
// ---------------------------------------------------------------------------
extern "C" void kernel_launch(void* const* d_in, const int* in_sizes, int n_in,
                              void* d_out, int out_size)
{
    const float* x    = (const float*)d_in[0];
    const void*  ei   = d_in[1];
    const float* W1   = (const float*)d_in[2];
    const float* b1   = (const float*)d_in[3];
    const float* W2   = (const float*)d_in[4];
    const float* b2   = (const float*)d_in[5];
    const float* W3   = (const float*)d_in[6];
    const float* b3   = (const float*)d_in[7];
    const float* Wlin = (const float*)d_in[8];
    const float* blin = (const float*)d_in[9];
    float*       out  = (float*)d_out;

    const int node_blocks = (N_NODES + 255) / 256;
    const int edge_blocks = (N_EDGES + 255) / 256;
    const int full_gemm_blocks = (N_NODES + 127) / 128;

    cudaStream_t sB;
    cudaStreamCreateWithFlags(&sB, cudaStreamNonBlocking);
    cudaEvent_t evScan, evFill, evA[NCHUNK], evB;
    cudaEventCreateWithFlags(&evScan, cudaEventDisableTiming);
    cudaEventCreateWithFlags(&evFill, cudaEventDisableTiming);
    cudaEventCreateWithFlags(&evB, cudaEventDisableTiming);
    for (int c = 0; c < NCHUNK; c++)
        cudaEventCreateWithFlags(&evA[c], cudaEventDisableTiming);

    // Prologue on stream A (default)
    k_prep      <<<node_blocks, 256>>>((const int*)ei);
    k_count     <<<edge_blocks, 256>>>(ei);
    k_block_sums<<<SCAN_NBLK, SCAN_B>>>();
    k_scan_bsums<<<1, 512>>>();
    k_scan_final<<<SCAN_NBLK, SCAN_B>>>();
    cudaEventRecord(evScan, 0);

    // Fork: CSR fill on B, layer-0 GEMM on A (both need only the scan)
    cudaStreamWaitEvent(sB, evScan, 0);
    k_csr_fill<<<edge_blocks, 256, 0, sB>>>(ei);
    cudaEventRecord(evFill, sB);

    k_gemm_layer<<<full_gemm_blocks, 256>>>(x, 0, W1, 0, N_NODES);
    cudaStreamWaitEvent(0, evFill, 0);

    const float* Wl[3] = {W1, W2, W3};
    const float* bl[3] = {b1, b2, b3};

    for (int l = 0; l < 3; l++) {
        // gathers chunked on A
        for (int c = 0; c < NCHUNK; c++) {
            int off = c * CHUNK;
            if (off >= N_NODES) { cudaEventRecord(evA[c], 0); continue; }
            int lim = off + CHUNK < N_NODES ? off + CHUNK : N_NODES;
            int nwarps = lim - off;
            int blocks = (nwarps * 32 + 255) / 256;
            k_gather<<<blocks, 256>>>(bl[l], l, off, lim);
            cudaEventRecord(evA[c], 0);
        }
        // next-stage GEMM per chunk on B (writes the OTHER h1 buffer)
        for (int c = 0; c < NCHUNK; c++) {
            int off = c * CHUNK;
            if (off >= N_NODES) continue;
            int lim = off + CHUNK < N_NODES ? off + CHUNK : N_NODES;
            int blocks = (lim - off + 127) / 128;
            cudaStreamWaitEvent(sB, evA[c], 0);
            if (l < 2)
                k_gemm_layer<<<blocks, 256, 0, sB>>>(x, l + 1, Wl[l + 1], off, lim);
            else
                k_gemm_final<<<blocks, 256, 0, sB>>>(Wlin, blin, out, off, lim);
        }
        cudaEventRecord(evB, sB);
        cudaStreamWaitEvent(0, evB, 0);   // gather(l+1) / graph leaf needs full GEMM
    }

    cudaEventDestroy(evScan);
    cudaEventDestroy(evFill);
    cudaEventDestroy(evB);
    for (int c = 0; c < NCHUNK; c++) cudaEventDestroy(evA[c]);
    cudaStreamDestroy(sB);
}

// round 14
// speedup vs baseline: 1.2049x; 1.2049x over previous
#include <cuda_runtime.h>
#include <cuda_fp16.h>
#include <cstdint>

#define N_NODES 100000
#define N_EDGES 1600000
#define EMB 128
#define HID 128
#define REPR 64
#define CAT 384

#define SCAN_B 256
#define SCAN_NBLK ((N_NODES + SCAN_B - 1) / SCAN_B)   // 391

// Scratch (device globals; no allocation APIs allowed)
__device__ int    g_is64;
__device__ int    g_cnt   [N_NODES];
__device__ int    g_cursor[N_NODES];
__device__ int    g_ro    [N_NODES];
__device__ int    g_adj   [N_EDGES];
__device__ int    g_bsum  [SCAN_NBLK];
__device__ int    g_boff  [SCAN_NBLK];
__device__ float  g_dinv  [N_NODES];
__device__ __half g_h1h   [(size_t)N_NODES * HID];  // fp16 h1 (layer0: unscaled)
__device__ __half g_xsh   [(size_t)N_NODES * CAT];  // fp16 JumpingKnowledge concat

// ---------------------------------------------------------------------------
// Helpers
// ---------------------------------------------------------------------------
__device__ __forceinline__ uint32_t tf32r(float f) {
    uint32_t u;
    asm("cvt.rna.tf32.f32 %0, %1;" : "=r"(u) : "f"(f));
    return u;
}

__device__ __forceinline__ void mma_tf32(float c[4], const uint32_t a[4],
                                         uint32_t b0, uint32_t b1) {
    asm volatile(
        "mma.sync.aligned.m16n8k8.row.col.f32.tf32.tf32.f32 "
        "{%0,%1,%2,%3}, {%4,%5,%6,%7}, {%8,%9}, {%0,%1,%2,%3};"
        : "+f"(c[0]), "+f"(c[1]), "+f"(c[2]), "+f"(c[3])
        : "r"(a[0]), "r"(a[1]), "r"(a[2]), "r"(a[3]), "r"(b0), "r"(b1));
}

__device__ __forceinline__ int edge_at(const void* ei, int idx) {
    if (g_is64) return (int)((const long long*)ei)[idx];
    return ((const int*)ei)[idx];
}

// ---------------------------------------------------------------------------
// Prep: zero counters; probe edge-index dtype (int64 nonneg < 2^32 has zero
// high words).
// ---------------------------------------------------------------------------
__global__ void k_prep(const int* __restrict__ ei32) {
    int i = blockIdx.x * blockDim.x + threadIdx.x;
    if (i < N_NODES) { g_cnt[i] = 0; g_cursor[i] = 0; }
    if (blockIdx.x == 0 && threadIdx.x == 0) {
        int is64 = 1;
        for (int k = 0; k < 256; k++) {
            if (ei32[2 * k + 1] != 0) { is64 = 0; break; }
        }
        g_is64 = is64;
    }
}

__global__ void k_count(const void* __restrict__ ei) {
    int e = blockIdx.x * blockDim.x + threadIdx.x;
    if (e < N_EDGES) {
        int c = edge_at(ei, N_EDGES + e);
        atomicAdd(&g_cnt[c], 1);
    }
}

__global__ void __launch_bounds__(SCAN_B) k_block_sums() {
    __shared__ int sdata[SCAN_B];
    int i = blockIdx.x * SCAN_B + threadIdx.x;
    int v = (i < N_NODES) ? g_cnt[i] : 0;
    sdata[threadIdx.x] = v;
    __syncthreads();
#pragma unroll
    for (int off = SCAN_B / 2; off > 0; off >>= 1) {
        if (threadIdx.x < off) sdata[threadIdx.x] += sdata[threadIdx.x + off];
        __syncthreads();
    }
    if (threadIdx.x == 0) g_bsum[blockIdx.x] = sdata[0];
}

__global__ void __launch_bounds__(512) k_scan_bsums() {
    __shared__ int s[512];
    int t = threadIdx.x;
    int v = (t < SCAN_NBLK) ? g_bsum[t] : 0;
    s[t] = v;
    __syncthreads();
    for (int off = 1; off < 512; off <<= 1) {
        int u = (t >= off) ? s[t - off] : 0;
        __syncthreads();
        s[t] += u;
        __syncthreads();
    }
    if (t < SCAN_NBLK) g_boff[t] = s[t] - v;   // exclusive
}

__global__ void __launch_bounds__(SCAN_B) k_scan_final() {
    __shared__ int s[SCAN_B];
    int t = threadIdx.x;
    int i = blockIdx.x * SCAN_B + t;
    int v = (i < N_NODES) ? g_cnt[i] : 0;
    s[t] = v;
    __syncthreads();
    for (int off = 1; off < SCAN_B; off <<= 1) {
        int u = (t >= off) ? s[t - off] : 0;
        __syncthreads();
        s[t] += u;
        __syncthreads();
    }
    if (i < N_NODES) {
        g_ro[i]   = g_boff[blockIdx.x] + s[t] - v;   // exclusive
        g_dinv[i] = rsqrtf(1.0f + (float)v);
    }
}

__global__ void k_csr_fill(const void* __restrict__ ei) {
    int e = blockIdx.x * blockDim.x + threadIdx.x;
    if (e < N_EDGES) {
        int r = edge_at(ei, e);
        int c = edge_at(ei, N_EDGES + e);
        int pos = atomicAdd(&g_cursor[c], 1);
        g_adj[g_ro[c] + pos] = r;
    }
}

// ---------------------------------------------------------------------------
// Layer GEMM (tf32): h1h = fp16( (A @ W) * s ), s = dinv[row] for layer>0,
// s = 1 for layer 0 (dinv not yet computed; gather applies it per neighbor).
// layer 0: A = x (fp32); layer > 0: A = g_xsh slice (fp16, exact in tf32)
// Block 128x128, BK=32, 8 warps as 4(m) x 2(n); warp tile 32x64.
// ---------------------------------------------------------------------------
__global__ void __launch_bounds__(256) k_gemm_layer(
    const float* __restrict__ x, int layer,
    const float* __restrict__ W)
{
    __shared__ float As[128][36];
    __shared__ float Ws[32][132];

    const int row0   = blockIdx.x * 128;
    const int tid    = threadIdx.x;
    const int wid    = tid >> 5;
    const int lane   = tid & 31;
    const int g      = lane >> 2;
    const int t      = lane & 3;
    const int warp_m = wid >> 1;
    const int warp_n = wid & 1;

    const __half* Ah = (layer > 0) ? (g_xsh + (layer - 1) * HID) : nullptr;

    float acc[2][8][4];
#pragma unroll
    for (int mt = 0; mt < 2; mt++)
#pragma unroll
        for (int nt = 0; nt < 8; nt++)
#pragma unroll
            for (int q = 0; q < 4; q++) acc[mt][nt][q] = 0.0f;

    for (int k0 = 0; k0 < 128; k0 += 32) {
#pragma unroll
        for (int p = 0; p < 4; p++) {
            int idx = tid + p * 256;
            int r   = idx >> 3;
            int c4  = (idx & 7) << 2;
            int gr  = row0 + r;
            float4 v = make_float4(0.f, 0.f, 0.f, 0.f);
            if (gr < N_NODES) {
                if (layer == 0) {
                    v = *(const float4*)(x + (size_t)gr * EMB + k0 + c4);
                    v.x = __uint_as_float(tf32r(v.x));
                    v.y = __uint_as_float(tf32r(v.y));
                    v.z = __uint_as_float(tf32r(v.z));
                    v.w = __uint_as_float(tf32r(v.w));
                } else {
                    uint2 u = *(const uint2*)(Ah + (size_t)gr * CAT + k0 + c4);
                    float2 f0 = __half22float2(*(__half2*)&u.x);
                    float2 f1 = __half22float2(*(__half2*)&u.y);
                    v = make_float4(f0.x, f0.y, f1.x, f1.y);
                }
            }
            *(float4*)&As[r][c4] = v;
        }
#pragma unroll
        for (int p = 0; p < 4; p++) {
            int idx = tid + p * 256;
            int r   = idx >> 5;
            int c4  = (idx & 31) << 2;
            float4 v = *(const float4*)(W + (size_t)(k0 + r) * 128 + c4);
            v.x = __uint_as_float(tf32r(v.x));
            v.y = __uint_as_float(tf32r(v.y));
            v.z = __uint_as_float(tf32r(v.z));
            v.w = __uint_as_float(tf32r(v.w));
            *(float4*)&Ws[r][c4] = v;
        }
        __syncthreads();

#pragma unroll
        for (int kc = 0; kc < 4; kc++) {
            int kb = kc * 8;
            uint32_t afr[2][4];
#pragma unroll
            for (int mt = 0; mt < 2; mt++) {
                int mrow = warp_m * 32 + mt * 16;
                afr[mt][0] = __float_as_uint(As[mrow + g    ][kb + t    ]);
                afr[mt][1] = __float_as_uint(As[mrow + g + 8][kb + t    ]);
                afr[mt][2] = __float_as_uint(As[mrow + g    ][kb + t + 4]);
                afr[mt][3] = __float_as_uint(As[mrow + g + 8][kb + t + 4]);
            }
#pragma unroll
            for (int nt = 0; nt < 8; nt++) {
                int nc = warp_n * 64 + nt * 8;
                uint32_t b0 = __float_as_uint(Ws[kb + t    ][nc + g]);
                uint32_t b1 = __float_as_uint(Ws[kb + t + 4][nc + g]);
                mma_tf32(acc[0][nt], afr[0], b0, b1);
                mma_tf32(acc[1][nt], afr[1], b0, b1);
            }
        }
        __syncthreads();
    }

    // Epilogue: scale by dinv[row] (layers > 0 only), store fp16
#pragma unroll
    for (int mt = 0; mt < 2; mt++) {
        int r0 = row0 + warp_m * 32 + mt * 16 + g;
        int r1 = r0 + 8;
        bool ok0 = (r0 < N_NODES), ok1 = (r1 < N_NODES);
        float d0 = 1.0f, d1 = 1.0f;
        if (layer > 0) {
            d0 = ok0 ? g_dinv[r0] : 0.f;
            d1 = ok1 ? g_dinv[r1] : 0.f;
        }
#pragma unroll
        for (int nt = 0; nt < 8; nt++) {
            int col = warp_n * 64 + nt * 8 + 2 * t;
            if (ok0) {
                __half2 h = __floats2half2_rn(acc[mt][nt][0] * d0, acc[mt][nt][1] * d0);
                *(__half2*)(g_h1h + (size_t)r0 * 128 + col) = h;
            }
            if (ok1) {
                __half2 h = __floats2half2_rn(acc[mt][nt][2] * d1, acc[mt][nt][3] * d1);
                *(__half2*)(g_h1h + (size_t)r1 * 128 + col) = h;
            }
        }
    }
}

// ---------------------------------------------------------------------------
// Gather aggregation: one warp per node; lane holds 4 features (uint2 = 2x
// half2). Accumulate fp32. Unroll 8. Output fp16 into g_xsh.
// layer 0: h1 is UNSCALED -> multiply each neighbor by dinv[nbr] (FMA),
// self term by dinv[w]. layers > 0: h1 pre-scaled, plain adds.
// ---------------------------------------------------------------------------
__global__ void __launch_bounds__(256) k_gather(
    const float* __restrict__ b, int layer)
{
    int w    = (blockIdx.x * 256 + threadIdx.x) >> 5;
    int lane = threadIdx.x & 31;
    if (w >= N_NODES) return;

    const bool l0 = (layer == 0);
    float dw = g_dinv[w];

    float4 acc;
    {
        uint2 u = ((const uint2*)(g_h1h + (size_t)w * 128))[lane];
        float2 f0 = __half22float2(*(__half2*)&u.x);
        float2 f1 = __half22float2(*(__half2*)&u.y);
        float s = l0 ? dw : 1.0f;
        acc = make_float4(f0.x * s, f0.y * s, f1.x * s, f1.y * s);
    }

    int start = g_ro[w];
    int deg   = g_cnt[w];

    int k = 0;
    for (; k + 7 < deg; k += 8) {
        int n[8];
#pragma unroll
        for (int j = 0; j < 8; j++) n[j] = g_adj[start + k + j];
        uint2 u[8];
#pragma unroll
        for (int j = 0; j < 8; j++)
            u[j] = ((const uint2*)(g_h1h + (size_t)n[j] * 128))[lane];
        if (l0) {
            float dv[8];
#pragma unroll
            for (int j = 0; j < 8; j++) dv[j] = g_dinv[n[j]];
#pragma unroll
            for (int j = 0; j < 8; j++) {
                float2 f0 = __half22float2(*(__half2*)&u[j].x);
                float2 f1 = __half22float2(*(__half2*)&u[j].y);
                acc.x = fmaf(f0.x, dv[j], acc.x);
                acc.y = fmaf(f0.y, dv[j], acc.y);
                acc.z = fmaf(f1.x, dv[j], acc.z);
                acc.w = fmaf(f1.y, dv[j], acc.w);
            }
        } else {
#pragma unroll
            for (int j = 0; j < 8; j++) {
                float2 f0 = __half22float2(*(__half2*)&u[j].x);
                float2 f1 = __half22float2(*(__half2*)&u[j].y);
                acc.x += f0.x; acc.y += f0.y; acc.z += f1.x; acc.w += f1.y;
            }
        }
    }
    for (; k < deg; k++) {
        int n0 = g_adj[start + k];
        uint2 u0 = ((const uint2*)(g_h1h + (size_t)n0 * 128))[lane];
        float2 f0 = __half22float2(*(__half2*)&u0.x);
        float2 f1 = __half22float2(*(__half2*)&u0.y);
        float dv = l0 ? g_dinv[n0] : 1.0f;
        acc.x = fmaf(f0.x, dv, acc.x);
        acc.y = fmaf(f0.y, dv, acc.y);
        acc.z = fmaf(f1.x, dv, acc.z);
        acc.w = fmaf(f1.y, dv, acc.w);
    }

    float4 bv = ((const float4*)b)[lane];
    float4 r;
    r.x = fmaxf(fmaf(acc.x, dw, bv.x), 0.f);
    r.y = fmaxf(fmaf(acc.y, dw, bv.y), 0.f);
    r.z = fmaxf(fmaf(acc.z, dw, bv.z), 0.f);
    r.w = fmaxf(fmaf(acc.w, dw, bv.w), 0.f);

    uint2 o;
    __half2 h0 = __floats2half2_rn(r.x, r.y);
    __half2 h1 = __floats2half2_rn(r.z, r.w);
    o.x = *(uint32_t*)&h0;
    o.y = *(uint32_t*)&h1;
    *((uint2*)(g_xsh + (size_t)w * CAT + layer * HID) + lane) = o;
}

// ---------------------------------------------------------------------------
// Final GEMM (tf32): out = xsh @ Wlin + blin  (xsh: [M,384] fp16)
// Block 128x64, BK=32, 8 warps as 8(m) x 1(n); warp tile 16x64.
// ---------------------------------------------------------------------------
__global__ void __launch_bounds__(256) k_gemm_final(
    const float* __restrict__ W,
    const float* __restrict__ b,
    float* __restrict__ out)
{
    __shared__ float As[128][36];
    __shared__ float Ws[32][68];

    const int row0 = blockIdx.x * 128;
    const int tid  = threadIdx.x;
    const int wid  = tid >> 5;
    const int lane = tid & 31;
    const int g    = lane >> 2;
    const int t    = lane & 3;

    float acc[8][4];
#pragma unroll
    for (int nt = 0; nt < 8; nt++)
#pragma unroll
        for (int q = 0; q < 4; q++) acc[nt][q] = 0.0f;

    for (int k0 = 0; k0 < CAT; k0 += 32) {
#pragma unroll
        for (int p = 0; p < 4; p++) {
            int idx = tid + p * 256;
            int r   = idx >> 3;
            int c4  = (idx & 7) << 2;
            int gr  = row0 + r;
            float4 v = make_float4(0.f, 0.f, 0.f, 0.f);
            if (gr < N_NODES) {
                uint2 u = *(const uint2*)(g_xsh + (size_t)gr * CAT + k0 + c4);
                float2 f0 = __half22float2(*(__half2*)&u.x);
                float2 f1 = __half22float2(*(__half2*)&u.y);
                v = make_float4(f0.x, f0.y, f1.x, f1.y);
            }
            *(float4*)&As[r][c4] = v;
        }
#pragma unroll
        for (int p = 0; p < 2; p++) {
            int idx = tid + p * 256;
            int r   = idx >> 4;
            int c4  = (idx & 15) << 2;
            float4 v = *(const float4*)(W + (size_t)(k0 + r) * REPR + c4);
            v.x = __uint_as_float(tf32r(v.x));
            v.y = __uint_as_float(tf32r(v.y));
            v.z = __uint_as_float(tf32r(v.z));
            v.w = __uint_as_float(tf32r(v.w));
            *(float4*)&Ws[r][c4] = v;
        }
        __syncthreads();

#pragma unroll
        for (int kc = 0; kc < 4; kc++) {
            int kb = kc * 8;
            uint32_t afr[4];
            int mrow = wid * 16;
            afr[0] = __float_as_uint(As[mrow + g    ][kb + t    ]);
            afr[1] = __float_as_uint(As[mrow + g + 8][kb + t    ]);
            afr[2] = __float_as_uint(As[mrow + g    ][kb + t + 4]);
            afr[3] = __float_as_uint(As[mrow + g + 8][kb + t + 4]);
#pragma unroll
            for (int nt = 0; nt < 8; nt++) {
                int nc = nt * 8;
                uint32_t b0 = __float_as_uint(Ws[kb + t    ][nc + g]);
                uint32_t b1 = __float_as_uint(Ws[kb + t + 4][nc + g]);
                mma_tf32(acc[nt], afr, b0, b1);
            }
        }
        __syncthreads();
    }

    int r0 = row0 + wid * 16 + g;
    int r1 = r0 + 8;
    bool ok0 = (r0 < N_NODES), ok1 = (r1 < N_NODES);
#pragma unroll
    for (int nt = 0; nt < 8; nt++) {
        int col = nt * 8 + 2 * t;
        float2 bv = *(const float2*)(b + col);
        if (ok0) {
            float2 v = make_float2(acc[nt][0] + bv.x, acc[nt][1] + bv.y);
            *(float2*)(out + (size_t)r0 * REPR + col) = v;
        }
        if (ok1) {
            float2 v = make_float2(acc[nt][2] + bv.x, acc[nt][3] + bv.y);
            *(float2*)(out + (size_t)r1 * REPR + col) = v;
        }
    }
}

// ---------------------------------------------------------------------------
// Launch. Layer-0 GEMM depends ONLY on x and W1 (dinv deferred to gather),
// so it runs on stream B from t=0, fully hidden behind the CSR prologue on
// stream A. Everything after the join is the proven sequential r11 chain.
// ---------------------------------------------------------------------------
extern "C" void kernel_launch(void* const* d_in, const int* in_sizes, int n_in,
                              void* d_out, int out_size)
{
    const float* x    = (const float*)d_in[0];
    const void*  ei   = d_in[1];
    const float* W1   = (const float*)d_in[2];
    const float* b1   = (const float*)d_in[3];
    const float* W2   = (const float*)d_in[4];
    const float* b2   = (const float*)d_in[5];
    const float* W3   = (const float*)d_in[6];
    const float* b3   = (const float*)d_in[7];
    const float* Wlin = (const float*)d_in[8];
    const float* blin = (const float*)d_in[9];
    float*       out  = (float*)d_out;

    const int node_blocks = (N_NODES + 255) / 256;
    const int edge_blocks = (N_EDGES + 255) / 256;
    const int gemm_blocks = (N_NODES + 127) / 128;
    const int warp_blocks = (N_NODES * 32 + 255) / 256;

    cudaStream_t sB;
    cudaStreamCreateWithFlags(&sB, cudaStreamNonBlocking);
    cudaEvent_t evFork, evG0;
    cudaEventCreateWithFlags(&evFork, cudaEventDisableTiming);
    cudaEventCreateWithFlags(&evG0, cudaEventDisableTiming);

    // Fork at t=0: layer-0 GEMM (unscaled) on stream B.
    cudaEventRecord(evFork, 0);
    cudaStreamWaitEvent(sB, evFork, 0);
    k_gemm_layer<<<gemm_blocks, 256, 0, sB>>>(x, 0, W1);
    cudaEventRecord(evG0, sB);

    // CSR prologue on stream A (default), concurrent with gemm0.
    k_prep      <<<node_blocks, 256>>>((const int*)ei);
    k_count     <<<edge_blocks, 256>>>(ei);
    k_block_sums<<<SCAN_NBLK, SCAN_B>>>();
    k_scan_bsums<<<1, 512>>>();
    k_scan_final<<<SCAN_NBLK, SCAN_B>>>();
    k_csr_fill  <<<edge_blocks, 256>>>(ei);

    // Join: gather(0) needs CSR (A) + h1 from gemm0 (B).
    cudaStreamWaitEvent(0, evG0, 0);

    const float* Wl[3] = {W1, W2, W3};
    const float* bl[3] = {b1, b2, b3};
    for (int l = 0; l < 3; l++) {
        k_gather<<<warp_blocks, 256>>>(bl[l], l);
        if (l < 2) k_gemm_layer<<<gemm_blocks, 256>>>(x, l + 1, Wl[l + 1]);
    }

    k_gemm_final<<<gemm_blocks, 256>>>(Wlin, blin, out);

    cudaEventDestroy(evFork);
    cudaEventDestroy(evG0);
    cudaStreamDestroy(sB);
}

// round 15
// speedup vs baseline: 1.2526x; 1.0397x over previous
#include <cuda_runtime.h>
#include <cuda_fp16.h>
#include <cstdint>

#define N_NODES 100000
#define N_EDGES 1600000
#define EMB 128
#define HID 128
#define REPR 64
#define CAT 384

#define SCAN_B 256
#define SCAN_NBLK ((N_NODES + SCAN_B - 1) / SCAN_B)   // 391

// Scratch (device globals; no allocation APIs allowed)
__device__ int    g_is64;
__device__ int    g_cnt   [N_NODES];
__device__ int    g_cursor[N_NODES];
__device__ int    g_ro    [N_NODES];
__device__ int    g_adj   [N_EDGES];
__device__ int    g_bsum  [SCAN_NBLK];
__device__ int    g_boff  [SCAN_NBLK];
__device__ float  g_dinv  [N_NODES];
__device__ __half g_h1h   [(size_t)N_NODES * HID];  // fp16 h1 (layer0: unscaled)
__device__ __half g_xsh   [(size_t)N_NODES * CAT];  // fp16 JumpingKnowledge concat

// ---------------------------------------------------------------------------
// Helpers
// ---------------------------------------------------------------------------
__device__ __forceinline__ uint32_t tf32r(float f) {
    uint32_t u;
    asm("cvt.rna.tf32.f32 %0, %1;" : "=r"(u) : "f"(f));
    return u;
}

__device__ __forceinline__ void mma_tf32(float c[4], const uint32_t a[4],
                                         uint32_t b0, uint32_t b1) {
    asm volatile(
        "mma.sync.aligned.m16n8k8.row.col.f32.tf32.tf32.f32 "
        "{%0,%1,%2,%3}, {%4,%5,%6,%7}, {%8,%9}, {%0,%1,%2,%3};"
        : "+f"(c[0]), "+f"(c[1]), "+f"(c[2]), "+f"(c[3])
        : "r"(a[0]), "r"(a[1]), "r"(a[2]), "r"(a[3]), "r"(b0), "r"(b1));
}

__device__ __forceinline__ int edge_at(const void* ei, int idx) {
    if (g_is64) return (int)((const long long*)ei)[idx];
    return ((const int*)ei)[idx];
}

// ---------------------------------------------------------------------------
// Prep: zero counters; probe edge-index dtype (int64 nonneg < 2^32 has zero
// high words).
// ---------------------------------------------------------------------------
__global__ void k_prep(const int* __restrict__ ei32) {
    int i = blockIdx.x * blockDim.x + threadIdx.x;
    if (i < N_NODES) { g_cnt[i] = 0; g_cursor[i] = 0; }
    if (blockIdx.x == 0 && threadIdx.x == 0) {
        int is64 = 1;
        for (int k = 0; k < 256; k++) {
            if (ei32[2 * k + 1] != 0) { is64 = 0; break; }
        }
        g_is64 = is64;
    }
}

__global__ void k_count(const void* __restrict__ ei) {
    int e = blockIdx.x * blockDim.x + threadIdx.x;
    if (e < N_EDGES) {
        int c = edge_at(ei, N_EDGES + e);
        atomicAdd(&g_cnt[c], 1);
    }
}

__global__ void __launch_bounds__(SCAN_B) k_block_sums() {
    __shared__ int sdata[SCAN_B];
    int i = blockIdx.x * SCAN_B + threadIdx.x;
    int v = (i < N_NODES) ? g_cnt[i] : 0;
    sdata[threadIdx.x] = v;
    __syncthreads();
#pragma unroll
    for (int off = SCAN_B / 2; off > 0; off >>= 1) {
        if (threadIdx.x < off) sdata[threadIdx.x] += sdata[threadIdx.x + off];
        __syncthreads();
    }
    if (threadIdx.x == 0) g_bsum[blockIdx.x] = sdata[0];
}

__global__ void __launch_bounds__(512) k_scan_bsums() {
    __shared__ int s[512];
    int t = threadIdx.x;
    int v = (t < SCAN_NBLK) ? g_bsum[t] : 0;
    s[t] = v;
    __syncthreads();
    for (int off = 1; off < 512; off <<= 1) {
        int u = (t >= off) ? s[t - off] : 0;
        __syncthreads();
        s[t] += u;
        __syncthreads();
    }
    if (t < SCAN_NBLK) g_boff[t] = s[t] - v;   // exclusive
}

__global__ void __launch_bounds__(SCAN_B) k_scan_final() {
    __shared__ int s[SCAN_B];
    int t = threadIdx.x;
    int i = blockIdx.x * SCAN_B + t;
    int v = (i < N_NODES) ? g_cnt[i] : 0;
    s[t] = v;
    __syncthreads();
    for (int off = 1; off < SCAN_B; off <<= 1) {
        int u = (t >= off) ? s[t - off] : 0;
        __syncthreads();
        s[t] += u;
        __syncthreads();
    }
    if (i < N_NODES) {
        g_ro[i]   = g_boff[blockIdx.x] + s[t] - v;   // exclusive
        g_dinv[i] = rsqrtf(1.0f + (float)v);
    }
}

__global__ void k_csr_fill(const void* __restrict__ ei) {
    int e = blockIdx.x * blockDim.x + threadIdx.x;
    if (e < N_EDGES) {
        int r = edge_at(ei, e);
        int c = edge_at(ei, N_EDGES + e);
        int pos = atomicAdd(&g_cursor[c], 1);
        g_adj[g_ro[c] + pos] = r;
    }
}

// ---------------------------------------------------------------------------
// Layer GEMM (tf32): h1h = fp16( (A @ W) * s ), s = dinv[row] for layer>0,
// s = 1 for layer 0 (dinv not yet computed; gather applies it per neighbor).
// layer 0: A = x (fp32); layer > 0: A = g_xsh slice (fp16, exact in tf32)
// ---------------------------------------------------------------------------
__global__ void __launch_bounds__(256) k_gemm_layer(
    const float* __restrict__ x, int layer,
    const float* __restrict__ W)
{
    __shared__ float As[128][36];
    __shared__ float Ws[32][132];

    const int row0   = blockIdx.x * 128;
    const int tid    = threadIdx.x;
    const int wid    = tid >> 5;
    const int lane   = tid & 31;
    const int g      = lane >> 2;
    const int t      = lane & 3;
    const int warp_m = wid >> 1;
    const int warp_n = wid & 1;

    const __half* Ah = (layer > 0) ? (g_xsh + (layer - 1) * HID) : nullptr;

    float acc[2][8][4];
#pragma unroll
    for (int mt = 0; mt < 2; mt++)
#pragma unroll
        for (int nt = 0; nt < 8; nt++)
#pragma unroll
            for (int q = 0; q < 4; q++) acc[mt][nt][q] = 0.0f;

    for (int k0 = 0; k0 < 128; k0 += 32) {
#pragma unroll
        for (int p = 0; p < 4; p++) {
            int idx = tid + p * 256;
            int r   = idx >> 3;
            int c4  = (idx & 7) << 2;
            int gr  = row0 + r;
            float4 v = make_float4(0.f, 0.f, 0.f, 0.f);
            if (gr < N_NODES) {
                if (layer == 0) {
                    v = *(const float4*)(x + (size_t)gr * EMB + k0 + c4);
                    v.x = __uint_as_float(tf32r(v.x));
                    v.y = __uint_as_float(tf32r(v.y));
                    v.z = __uint_as_float(tf32r(v.z));
                    v.w = __uint_as_float(tf32r(v.w));
                } else {
                    uint2 u = *(const uint2*)(Ah + (size_t)gr * CAT + k0 + c4);
                    float2 f0 = __half22float2(*(__half2*)&u.x);
                    float2 f1 = __half22float2(*(__half2*)&u.y);
                    v = make_float4(f0.x, f0.y, f1.x, f1.y);
                }
            }
            *(float4*)&As[r][c4] = v;
        }
#pragma unroll
        for (int p = 0; p < 4; p++) {
            int idx = tid + p * 256;
            int r   = idx >> 5;
            int c4  = (idx & 31) << 2;
            float4 v = *(const float4*)(W + (size_t)(k0 + r) * 128 + c4);
            v.x = __uint_as_float(tf32r(v.x));
            v.y = __uint_as_float(tf32r(v.y));
            v.z = __uint_as_float(tf32r(v.z));
            v.w = __uint_as_float(tf32r(v.w));
            *(float4*)&Ws[r][c4] = v;
        }
        __syncthreads();

#pragma unroll
        for (int kc = 0; kc < 4; kc++) {
            int kb = kc * 8;
            uint32_t afr[2][4];
#pragma unroll
            for (int mt = 0; mt < 2; mt++) {
                int mrow = warp_m * 32 + mt * 16;
                afr[mt][0] = __float_as_uint(As[mrow + g    ][kb + t    ]);
                afr[mt][1] = __float_as_uint(As[mrow + g + 8][kb + t    ]);
                afr[mt][2] = __float_as_uint(As[mrow + g    ][kb + t + 4]);
                afr[mt][3] = __float_as_uint(As[mrow + g + 8][kb + t + 4]);
            }
#pragma unroll
            for (int nt = 0; nt < 8; nt++) {
                int nc = warp_n * 64 + nt * 8;
                uint32_t b0 = __float_as_uint(Ws[kb + t    ][nc + g]);
                uint32_t b1 = __float_as_uint(Ws[kb + t + 4][nc + g]);
                mma_tf32(acc[0][nt], afr[0], b0, b1);
                mma_tf32(acc[1][nt], afr[1], b0, b1);
            }
        }
        __syncthreads();
    }

#pragma unroll
    for (int mt = 0; mt < 2; mt++) {
        int r0 = row0 + warp_m * 32 + mt * 16 + g;
        int r1 = r0 + 8;
        bool ok0 = (r0 < N_NODES), ok1 = (r1 < N_NODES);
        float d0 = 1.0f, d1 = 1.0f;
        if (layer > 0) {
            d0 = ok0 ? g_dinv[r0] : 0.f;
            d1 = ok1 ? g_dinv[r1] : 0.f;
        }
#pragma unroll
        for (int nt = 0; nt < 8; nt++) {
            int col = warp_n * 64 + nt * 8 + 2 * t;
            if (ok0) {
                __half2 h = __floats2half2_rn(acc[mt][nt][0] * d0, acc[mt][nt][1] * d0);
                *(__half2*)(g_h1h + (size_t)r0 * 128 + col) = h;
            }
            if (ok1) {
                __half2 h = __floats2half2_rn(acc[mt][nt][2] * d1, acc[mt][nt][3] * d1);
                *(__half2*)(g_h1h + (size_t)r1 * 128 + col) = h;
            }
        }
    }
}

// ---------------------------------------------------------------------------
// Gather aggregation: one warp per node; lane holds 4 features. fp32 accum,
// unroll 8. layer 0 applies dinv per neighbor (h1 unscaled).
// ---------------------------------------------------------------------------
__global__ void __launch_bounds__(256) k_gather(
    const float* __restrict__ b, int layer)
{
    int w    = (blockIdx.x * 256 + threadIdx.x) >> 5;
    int lane = threadIdx.x & 31;
    if (w >= N_NODES) return;

    const bool l0 = (layer == 0);
    float dw = g_dinv[w];

    float4 acc;
    {
        uint2 u = ((const uint2*)(g_h1h + (size_t)w * 128))[lane];
        float2 f0 = __half22float2(*(__half2*)&u.x);
        float2 f1 = __half22float2(*(__half2*)&u.y);
        float s = l0 ? dw : 1.0f;
        acc = make_float4(f0.x * s, f0.y * s, f1.x * s, f1.y * s);
    }

    int start = g_ro[w];
    int deg   = g_cnt[w];

    int k = 0;
    for (; k + 7 < deg; k += 8) {
        int n[8];
#pragma unroll
        for (int j = 0; j < 8; j++) n[j] = g_adj[start + k + j];
        uint2 u[8];
#pragma unroll
        for (int j = 0; j < 8; j++)
            u[j] = ((const uint2*)(g_h1h + (size_t)n[j] * 128))[lane];
        if (l0) {
            float dv[8];
#pragma unroll
            for (int j = 0; j < 8; j++) dv[j] = g_dinv[n[j]];
#pragma unroll
            for (int j = 0; j < 8; j++) {
                float2 f0 = __half22float2(*(__half2*)&u[j].x);
                float2 f1 = __half22float2(*(__half2*)&u[j].y);
                acc.x = fmaf(f0.x, dv[j], acc.x);
                acc.y = fmaf(f0.y, dv[j], acc.y);
                acc.z = fmaf(f1.x, dv[j], acc.z);
                acc.w = fmaf(f1.y, dv[j], acc.w);
            }
        } else {
#pragma unroll
            for (int j = 0; j < 8; j++) {
                float2 f0 = __half22float2(*(__half2*)&u[j].x);
                float2 f1 = __half22float2(*(__half2*)&u[j].y);
                acc.x += f0.x; acc.y += f0.y; acc.z += f1.x; acc.w += f1.y;
            }
        }
    }
    for (; k < deg; k++) {
        int n0 = g_adj[start + k];
        uint2 u0 = ((const uint2*)(g_h1h + (size_t)n0 * 128))[lane];
        float2 f0 = __half22float2(*(__half2*)&u0.x);
        float2 f1 = __half22float2(*(__half2*)&u0.y);
        float dv = l0 ? g_dinv[n0] : 1.0f;
        acc.x = fmaf(f0.x, dv, acc.x);
        acc.y = fmaf(f0.y, dv, acc.y);
        acc.z = fmaf(f1.x, dv, acc.z);
        acc.w = fmaf(f1.y, dv, acc.w);
    }

    float4 bv = ((const float4*)b)[lane];
    float4 r;
    r.x = fmaxf(fmaf(acc.x, dw, bv.x), 0.f);
    r.y = fmaxf(fmaf(acc.y, dw, bv.y), 0.f);
    r.z = fmaxf(fmaf(acc.z, dw, bv.z), 0.f);
    r.w = fmaxf(fmaf(acc.w, dw, bv.w), 0.f);

    uint2 o;
    __half2 h0 = __floats2half2_rn(r.x, r.y);
    __half2 h1 = __floats2half2_rn(r.z, r.w);
    o.x = *(uint32_t*)&h0;
    o.y = *(uint32_t*)&h1;
    *((uint2*)(g_xsh + (size_t)w * CAT + layer * HID) + lane) = o;
}

// ---------------------------------------------------------------------------
// Partial final GEMM (tf32): K-split of out = xs @ Wlin + blin.
// partial(layer): out (+)= xs[:, layer*128:+128] @ Wlin[layer*128:+128, :]
// accumulate=0: write with bias; accumulate=1: read-modify-write.
// Block 128x64, K=128, 8 warps as 8(m) x 1(n).
// ---------------------------------------------------------------------------
__global__ void __launch_bounds__(256) k_gemm_final_partial(
    const float* __restrict__ W,     // Wlin + layer*128*REPR
    const float* __restrict__ b,     // blin (used when accumulate==0)
    float* __restrict__ out,
    int layer, int accumulate)
{
    __shared__ float As[128][36];
    __shared__ float Ws[32][68];

    const int row0 = blockIdx.x * 128;
    const int tid  = threadIdx.x;
    const int wid  = tid >> 5;
    const int lane = tid & 31;
    const int g    = lane >> 2;
    const int t    = lane & 3;

    const __half* A = g_xsh + layer * HID;

    float acc[8][4];
#pragma unroll
    for (int nt = 0; nt < 8; nt++)
#pragma unroll
        for (int q = 0; q < 4; q++) acc[nt][q] = 0.0f;

    for (int k0 = 0; k0 < 128; k0 += 32) {
#pragma unroll
        for (int p = 0; p < 4; p++) {
            int idx = tid + p * 256;
            int r   = idx >> 3;
            int c4  = (idx & 7) << 2;
            int gr  = row0 + r;
            float4 v = make_float4(0.f, 0.f, 0.f, 0.f);
            if (gr < N_NODES) {
                uint2 u = *(const uint2*)(A + (size_t)gr * CAT + k0 + c4);
                float2 f0 = __half22float2(*(__half2*)&u.x);
                float2 f1 = __half22float2(*(__half2*)&u.y);
                v = make_float4(f0.x, f0.y, f1.x, f1.y);
            }
            *(float4*)&As[r][c4] = v;
        }
#pragma unroll
        for (int p = 0; p < 2; p++) {
            int idx = tid + p * 256;
            int r   = idx >> 4;
            int c4  = (idx & 15) << 2;
            float4 v = *(const float4*)(W + (size_t)(k0 + r) * REPR + c4);
            v.x = __uint_as_float(tf32r(v.x));
            v.y = __uint_as_float(tf32r(v.y));
            v.z = __uint_as_float(tf32r(v.z));
            v.w = __uint_as_float(tf32r(v.w));
            *(float4*)&Ws[r][c4] = v;
        }
        __syncthreads();

#pragma unroll
        for (int kc = 0; kc < 4; kc++) {
            int kb = kc * 8;
            uint32_t afr[4];
            int mrow = wid * 16;
            afr[0] = __float_as_uint(As[mrow + g    ][kb + t    ]);
            afr[1] = __float_as_uint(As[mrow + g + 8][kb + t    ]);
            afr[2] = __float_as_uint(As[mrow + g    ][kb + t + 4]);
            afr[3] = __float_as_uint(As[mrow + g + 8][kb + t + 4]);
#pragma unroll
            for (int nt = 0; nt < 8; nt++) {
                int nc = nt * 8;
                uint32_t b0 = __float_as_uint(Ws[kb + t    ][nc + g]);
                uint32_t b1 = __float_as_uint(Ws[kb + t + 4][nc + g]);
                mma_tf32(acc[nt], afr, b0, b1);
            }
        }
        __syncthreads();
    }

    int r0 = row0 + wid * 16 + g;
    int r1 = r0 + 8;
    bool ok0 = (r0 < N_NODES), ok1 = (r1 < N_NODES);
#pragma unroll
    for (int nt = 0; nt < 8; nt++) {
        int col = nt * 8 + 2 * t;
        if (accumulate) {
            if (ok0) {
                float2 o = *(float2*)(out + (size_t)r0 * REPR + col);
                o.x += acc[nt][0]; o.y += acc[nt][1];
                *(float2*)(out + (size_t)r0 * REPR + col) = o;
            }
            if (ok1) {
                float2 o = *(float2*)(out + (size_t)r1 * REPR + col);
                o.x += acc[nt][2]; o.y += acc[nt][3];
                *(float2*)(out + (size_t)r1 * REPR + col) = o;
            }
        } else {
            float2 bv = *(const float2*)(b + col);
            if (ok0) {
                float2 v = make_float2(acc[nt][0] + bv.x, acc[nt][1] + bv.y);
                *(float2*)(out + (size_t)r0 * REPR + col) = v;
            }
            if (ok1) {
                float2 v = make_float2(acc[nt][2] + bv.x, acc[nt][3] + bv.y);
                *(float2*)(out + (size_t)r1 * REPR + col) = v;
            }
        }
    }
}

// ---------------------------------------------------------------------------
// Launch. Main chain (stream A): prologue -> gather0 -> gemm1 -> gather1 ->
// gemm2 -> gather2. Stream B: gemm0 (unscaled, from t=0), then K-split final
// partials: partial(l) starts as soon as gather(l) lands, overlapping with
// the remaining main chain. Only partial2 sits on the tail.
// ---------------------------------------------------------------------------
extern "C" void kernel_launch(void* const* d_in, const int* in_sizes, int n_in,
                              void* d_out, int out_size)
{
    const float* x    = (const float*)d_in[0];
    const void*  ei   = d_in[1];
    const float* W1   = (const float*)d_in[2];
    const float* b1   = (const float*)d_in[3];
    const float* W2   = (const float*)d_in[4];
    const float* b2   = (const float*)d_in[5];
    const float* W3   = (const float*)d_in[6];
    const float* b3   = (const float*)d_in[7];
    const float* Wlin = (const float*)d_in[8];
    const float* blin = (const float*)d_in[9];
    float*       out  = (float*)d_out;

    const int node_blocks = (N_NODES + 255) / 256;
    const int edge_blocks = (N_EDGES + 255) / 256;
    const int gemm_blocks = (N_NODES + 127) / 128;
    const int warp_blocks = (N_NODES * 32 + 255) / 256;

    cudaStream_t sB;
    cudaStreamCreateWithFlags(&sB, cudaStreamNonBlocking);
    cudaEvent_t evFork, evG0, evA[3], evBend;
    cudaEventCreateWithFlags(&evFork, cudaEventDisableTiming);
    cudaEventCreateWithFlags(&evG0, cudaEventDisableTiming);
    cudaEventCreateWithFlags(&evBend, cudaEventDisableTiming);
    for (int l = 0; l < 3; l++)
        cudaEventCreateWithFlags(&evA[l], cudaEventDisableTiming);

    // Fork at t=0: layer-0 GEMM (unscaled) on stream B.
    cudaEventRecord(evFork, 0);
    cudaStreamWaitEvent(sB, evFork, 0);
    k_gemm_layer<<<gemm_blocks, 256, 0, sB>>>(x, 0, W1);
    cudaEventRecord(evG0, sB);

    // CSR prologue on stream A, concurrent with gemm0.
    k_prep      <<<node_blocks, 256>>>((const int*)ei);
    k_count     <<<edge_blocks, 256>>>(ei);
    k_block_sums<<<SCAN_NBLK, SCAN_B>>>();
    k_scan_bsums<<<1, 512>>>();
    k_scan_final<<<SCAN_NBLK, SCAN_B>>>();
    k_csr_fill  <<<edge_blocks, 256>>>(ei);

    // Join: gather(0) needs CSR (A) + h1 from gemm0 (B).
    cudaStreamWaitEvent(0, evG0, 0);

    const float* Wl[3] = {W1, W2, W3};
    const float* bl[3] = {b1, b2, b3};
    for (int l = 0; l < 3; l++) {
        k_gather<<<warp_blocks, 256>>>(bl[l], l);
        cudaEventRecord(evA[l], 0);
        // Final-GEMM partial for this xs slice on stream B (serialized on B).
        cudaStreamWaitEvent(sB, evA[l], 0);
        k_gemm_final_partial<<<gemm_blocks, 256, 0, sB>>>(
            Wlin + (size_t)l * HID * REPR, blin, out, l, l > 0 ? 1 : 0);
        if (l < 2) k_gemm_layer<<<gemm_blocks, 256>>>(x, l + 1, Wl[l + 1]);
    }

    // Graph leaf on the capture stream: join B.
    cudaEventRecord(evBend, sB);
    cudaStreamWaitEvent(0, evBend, 0);

    cudaEventDestroy(evFork);
    cudaEventDestroy(evG0);
    cudaEventDestroy(evBend);
    for (int l = 0; l < 3; l++) cudaEventDestroy(evA[l]);
    cudaStreamDestroy(sB);
}